// round 16
// baseline (speedup 1.0000x reference)
#include <cuda_runtime.h>
#include <cuda_bf16.h>
#include <cstdint>
#include <cstddef>

// Problem constants
#define B_  2
#define L_  4096
#define D_  512
#define H_  8
#define DK_ 64
#define M_  (B_*L_)
#define NT_ (L_/64)

// Scratch (static device globals — allocation-free per harness rules)
__device__ __align__(16) unsigned short g_Qh[(size_t)B_*H_*L_*DK_];  // pre-scaled by 1/8
__device__ __align__(16) unsigned short g_Ql[(size_t)B_*H_*L_*DK_];
__device__ __align__(16) unsigned short g_xh[(size_t)M_*D_];
__device__ __align__(16) unsigned short g_xl[(size_t)M_*D_];
__device__ __align__(16) unsigned short g_Wh[(size_t)4*D_*D_];   // Wq,Wk,Wv,Wo
__device__ __align__(16) unsigned short g_Wl[(size_t)4*D_*D_];
__device__ __align__(16) unsigned short g_Oh[(size_t)M_*D_];
__device__ __align__(16) unsigned short g_Ol[(size_t)M_*D_];
// Pre-swizzled split-bf16 K/V tiles (zero-init → safe tails; masked rows never written)
__device__ __align__(16) unsigned char g_Khs[(size_t)B_*H_*NT_*8192];
__device__ __align__(16) unsigned char g_Kls[(size_t)B_*H_*NT_*8192];
__device__ __align__(16) unsigned char g_Vhs[(size_t)B_*H_*NT_*8192];
__device__ __align__(16) unsigned char g_Vls[(size_t)B_*H_*NT_*8192];
__device__ int g_ipos[B_][L_];   // l -> compacted position, or -1 if masked
__device__ int g_nvalid[B_];

// ---------------------------------------------------------------------------
// bf16-split + MMA helpers
// ---------------------------------------------------------------------------
__device__ __forceinline__ uint32_t pack_hi2(float x0, float x1) {
    uint32_t r;
    asm("prmt.b32 %0, %1, %2, 0x7632;" : "=r"(r)
        : "r"(__float_as_uint(x0)), "r"(__float_as_uint(x1)));
    return r;
}
__device__ __forceinline__ float hi_part(float x) {
    return __uint_as_float(__float_as_uint(x) & 0xFFFF0000u);
}
__device__ __forceinline__ uint32_t pack_rn2(float x0, float x1) {
    uint32_t r;
    asm("cvt.rn.bf16x2.f32 %0, %1, %2;" : "=r"(r) : "f"(x1), "f"(x0));
    return r;
}
__device__ __forceinline__ void mma16816(float* d, const uint32_t* a,
                                         uint32_t b0, uint32_t b1) {
    asm volatile(
        "mma.sync.aligned.m16n8k16.row.col.f32.bf16.bf16.f32 "
        "{%0,%1,%2,%3},{%4,%5,%6,%7},{%8,%9},{%0,%1,%2,%3};"
        : "+f"(d[0]), "+f"(d[1]), "+f"(d[2]), "+f"(d[3])
        : "r"(a[0]), "r"(a[1]), "r"(a[2]), "r"(a[3]), "r"(b0), "r"(b1));
}
__device__ __forceinline__ void ldsm4(uint32_t& r0, uint32_t& r1, uint32_t& r2,
                                      uint32_t& r3, uint32_t addr) {
    asm volatile("ldmatrix.sync.aligned.m8n8.x4.shared.b16 {%0,%1,%2,%3}, [%4];"
                 : "=r"(r0), "=r"(r1), "=r"(r2), "=r"(r3) : "r"(addr));
}
__device__ __forceinline__ void ldsm4t(uint32_t& r0, uint32_t& r1, uint32_t& r2,
                                       uint32_t& r3, uint32_t addr) {
    asm volatile("ldmatrix.sync.aligned.m8n8.x4.trans.shared.b16 {%0,%1,%2,%3}, [%4];"
                 : "=r"(r0), "=r"(r1), "=r"(r2), "=r"(r3) : "r"(addr));
}
__device__ __forceinline__ uint32_t smem_u32(const void* p) {
    return (uint32_t)__cvta_generic_to_shared(p);
}
__device__ __forceinline__ void cpasync16(uint32_t saddr, const void* gptr) {
    asm volatile("cp.async.cg.shared.global [%0], [%1], 16;" :: "r"(saddr), "l"(gptr));
}
__device__ __forceinline__ uint32_t swz(int key, int dimbyte) {
    uint32_t off = (uint32_t)(key * 128 + dimbyte);
    return off ^ ((uint32_t)(key & 7) << 4);
}

// ---------------------------------------------------------------------------
// fp32 -> split bf16 converters
// ---------------------------------------------------------------------------
__global__ __launch_bounds__(256) void split_f32(
    const float* __restrict__ src,
    unsigned short* __restrict__ dh, unsigned short* __restrict__ dl)
{
    const size_t i = ((size_t)blockIdx.x * 256 + threadIdx.x) * 8;
    const float4 a = *(const float4*)(src + i);
    const float4 b = *(const float4*)(src + i + 4);
    const float f[8] = {a.x, a.y, a.z, a.w, b.x, b.y, b.z, b.w};
    uint4 Hv, Lv;
    Hv.x = pack_hi2(f[0], f[1]); Hv.y = pack_hi2(f[2], f[3]);
    Hv.z = pack_hi2(f[4], f[5]); Hv.w = pack_hi2(f[6], f[7]);
    Lv.x = pack_rn2(f[0]-hi_part(f[0]), f[1]-hi_part(f[1]));
    Lv.y = pack_rn2(f[2]-hi_part(f[2]), f[3]-hi_part(f[3]));
    Lv.z = pack_rn2(f[4]-hi_part(f[4]), f[5]-hi_part(f[5]));
    Lv.w = pack_rn2(f[6]-hi_part(f[6]), f[7]-hi_part(f[7]));
    *(uint4*)(dh + i) = Hv;
    *(uint4*)(dl + i) = Lv;
}

__global__ __launch_bounds__(256) void split_w4(
    const float* __restrict__ Wq, const float* __restrict__ Wk,
    const float* __restrict__ Wv, const float* __restrict__ Wo,
    unsigned short* __restrict__ dh, unsigned short* __restrict__ dl)
{
    const int which = blockIdx.y;
    const float* src = (which == 0) ? Wq : (which == 1) ? Wk : (which == 2) ? Wv : Wo;
    const size_t base = (size_t)which * D_ * D_;
    const size_t i = ((size_t)blockIdx.x * 256 + threadIdx.x) * 8;
    const float4 a = *(const float4*)(src + i);
    const float4 b = *(const float4*)(src + i + 4);
    const float f[8] = {a.x, a.y, a.z, a.w, b.x, b.y, b.z, b.w};
    uint4 Hv, Lv;
    Hv.x = pack_hi2(f[0], f[1]); Hv.y = pack_hi2(f[2], f[3]);
    Hv.z = pack_hi2(f[4], f[5]); Hv.w = pack_hi2(f[6], f[7]);
    Lv.x = pack_rn2(f[0]-hi_part(f[0]), f[1]-hi_part(f[1]));
    Lv.y = pack_rn2(f[2]-hi_part(f[2]), f[3]-hi_part(f[3]));
    Lv.z = pack_rn2(f[4]-hi_part(f[4]), f[5]-hi_part(f[5]));
    Lv.w = pack_rn2(f[6]-hi_part(f[6]), f[7]-hi_part(f[7]));
    *(uint4*)(dh + base + i) = Hv;
    *(uint4*)(dl + base + i) = Lv;
}

// ---------------------------------------------------------------------------
// Tensor-core split-bf16 GEMM core (cp.async double-buffered, BK=64).
// Block 128x64, 8 warps (4m x 2n), warp tile 32x32 = 2x4 m16n8 tiles.
// smem 96KB: [Ah 2st|Al 2st|Wh 2st|Wl 2st] -> 2 CTAs/SM.
// ---------------------------------------------------------------------------
#define GEMM_TC_SMEM(AHP, ALP, WHP, WLP)                                      \
    extern __shared__ unsigned char smem[];                                   \
    const int t = threadIdx.x;                                                \
    const int lane = t & 31, warp = t >> 5;                                   \
    const int wm = warp & 3, wn = warp >> 2;                                  \
    const int m0 = blockIdx.y * 128;                                          \
    const int n0 = blockIdx.x * 64;                                           \
    const int g = lane >> 2, tc = (lane & 3) * 2;                             \
    const uint32_t sb = smem_u32(smem);                                       \
    const int mm = lane >> 3, ii = lane & 7;                                  \
    float acc[2][4][4];                                                       \
    _Pragma("unroll")                                                         \
    for (int i = 0; i < 2; i++)                                               \
        _Pragma("unroll")                                                     \
        for (int j = 0; j < 4; j++)                                           \
            _Pragma("unroll")                                                 \
            for (int c = 0; c < 4; c++) acc[i][j][c] = 0.0f;                  \
    uint32_t sofA[4]; const unsigned char* gA[4];                             \
    _Pragma("unroll")                                                         \
    for (int r = 0; r < 4; r++) {                                             \
        const int item = t + r * 256;                                         \
        const int rowx = item >> 3, oc = item & 7;                            \
        sofA[r] = swz(rowx, oc * 16);                                         \
        gA[r] = (const unsigned char*)(AHP)                                   \
                + ((size_t)(m0 + rowx) * D_ + oc * 8) * 2;                    \
    }                                                                         \
    uint32_t sofW[2]; const unsigned char* gW[2];                             \
    _Pragma("unroll")                                                         \
    for (int r = 0; r < 2; r++) {                                             \
        const int item = t + r * 256;                                         \
        const int rowx = item >> 3, oc = item & 7;                            \
        sofW[r] = swz(rowx, oc * 16);                                         \
        gW[r] = (const unsigned char*)(WHP)                                   \
                + ((size_t)(n0 + rowx) * D_ + oc * 8) * 2;                    \
    }                                                                         \
    const ptrdiff_t dAL = (const unsigned char*)(ALP) - (const unsigned char*)(AHP); \
    const ptrdiff_t dWL = (const unsigned char*)(WLP) - (const unsigned char*)(WHP); \
    _Pragma("unroll")                                                         \
    for (int r = 0; r < 4; r++) {                                             \
        cpasync16(sb +     0 + sofA[r], gA[r]);                               \
        cpasync16(sb + 32768 + sofA[r], gA[r] + dAL);                         \
    }                                                                         \
    _Pragma("unroll")                                                         \
    for (int r = 0; r < 2; r++) {                                             \
        cpasync16(sb + 65536 + sofW[r], gW[r]);                               \
        cpasync16(sb + 81920 + sofW[r], gW[r] + dWL);                         \
    }                                                                         \
    asm volatile("cp.async.commit_group;");                                   \
    _Pragma("unroll")                                                         \
    for (int kt = 0; kt < 8; kt++) {                                          \
        const int st = kt & 1;                                                \
        if (kt + 1 < 8) {                                                     \
            const uint32_t sA = (uint32_t)((st ^ 1) * 16384);                 \
            const uint32_t sW = (uint32_t)((st ^ 1) * 8192);                  \
            const size_t kb = (size_t)(kt + 1) * 128;                         \
            _Pragma("unroll")                                                 \
            for (int r = 0; r < 4; r++) {                                     \
                cpasync16(sb +     0 + sA + sofA[r], gA[r] + kb);             \
                cpasync16(sb + 32768 + sA + sofA[r], gA[r] + dAL + kb);       \
            }                                                                 \
            _Pragma("unroll")                                                 \
            for (int r = 0; r < 2; r++) {                                     \
                cpasync16(sb + 65536 + sW + sofW[r], gW[r] + kb);             \
                cpasync16(sb + 81920 + sW + sofW[r], gW[r] + dWL + kb);       \
            }                                                                 \
            asm volatile("cp.async.commit_group;");                           \
            asm volatile("cp.async.wait_group 1;");                           \
        } else {                                                              \
            asm volatile("cp.async.wait_group 0;");                           \
        }                                                                     \
        __syncthreads();                                                      \
        const uint32_t bAh = sb +     0 + st * 16384;                         \
        const uint32_t bAl = sb + 32768 + st * 16384;                         \
        const uint32_t bWh = sb + 65536 + st * 8192;                          \
        const uint32_t bWl = sb + 81920 + st * 8192;                          \
        _Pragma("unroll")                                                     \
        for (int ks = 0; ks < 4; ks++) {                                      \
            const int dby = ks * 32 + (mm & 1) * 16;                          \
            uint32_t ah[2][4], al[2][4];                                      \
            _Pragma("unroll")                                                 \
            for (int mt = 0; mt < 2; mt++) {                                  \
                const int key = wm * 32 + mt * 16 + (mm >> 1) * 8 + ii;       \
                const uint32_t po = swz(key, dby);                            \
                uint32_t r0, r1, r2, r3;                                      \
                ldsm4(r0, r1, r2, r3, bAh + po);                              \
                ah[mt][0] = r0; ah[mt][1] = r2; ah[mt][2] = r1; ah[mt][3] = r3; \
                ldsm4(r0, r1, r2, r3, bAl + po);                              \
                al[mt][0] = r0; al[mt][1] = r2; al[mt][2] = r1; al[mt][3] = r3; \
            }                                                                 \
            uint32_t whf[2][4], wlf[2][4];                                    \
            _Pragma("unroll")                                                 \
            for (int ng = 0; ng < 2; ng++) {                                  \
                const int key = wn * 32 + ng * 16 + (mm >> 1) * 8 + ii;       \
                const uint32_t po = swz(key, dby);                            \
                ldsm4(whf[ng][0], whf[ng][1], whf[ng][2], whf[ng][3], bWh + po); \
                ldsm4(wlf[ng][0], wlf[ng][1], wlf[ng][2], wlf[ng][3], bWl + po); \
            }                                                                 \
            _Pragma("unroll")                                                 \
            for (int mt = 0; mt < 2; mt++)                                    \
                _Pragma("unroll")                                             \
                for (int nt = 0; nt < 4; nt++)                                \
                    mma16816(acc[mt][nt], ah[mt],                             \
                             whf[nt>>1][(nt&1)*2], whf[nt>>1][(nt&1)*2+1]);   \
            _Pragma("unroll")                                                 \
            for (int mt = 0; mt < 2; mt++)                                    \
                _Pragma("unroll")                                             \
                for (int nt = 0; nt < 4; nt++)                                \
                    mma16816(acc[mt][nt], ah[mt],                             \
                             wlf[nt>>1][(nt&1)*2], wlf[nt>>1][(nt&1)*2+1]);   \
            _Pragma("unroll")                                                 \
            for (int mt = 0; mt < 2; mt++)                                    \
                _Pragma("unroll")                                             \
                for (int nt = 0; nt < 4; nt++)                                \
                    mma16816(acc[mt][nt], al[mt],                             \
                             whf[nt>>1][(nt&1)*2], whf[nt>>1][(nt&1)*2+1]);   \
        }                                                                     \
        __syncthreads();                                                      \
    }

// QKV projection: Q -> split-bf16 pre-scaled [B,H,L,dk]; K/V -> pre-swizzled
// split-bf16 compacted tiles (masked rows skipped; tails stay zero).
__global__ __launch_bounds__(256, 2) void qkv_gemm_tc(
    const float* __restrict__ bq, const float* __restrict__ bk,
    const float* __restrict__ bv)
{
    const int which = blockIdx.z;
    const unsigned short* Wh = g_Wh + (size_t)which * D_ * D_;
    const unsigned short* Wl = g_Wl + (size_t)which * D_ * D_;
    const float* bias = (which == 0) ? bq : ((which == 1) ? bk : bv);

    GEMM_TC_SMEM(g_xh, g_xl, Wh, Wl)

    if (which == 0) {
#pragma unroll
        for (int mt = 0; mt < 2; mt++) {
            const int r0 = m0 + wm*32 + mt*16 + g, r1 = r0 + 8;
            const int bb0 = r0 >> 12, l0v = r0 & (L_-1);
            const int bb1 = r1 >> 12, l1v = r1 & (L_-1);
#pragma unroll
            for (int nt = 0; nt < 4; nt++) {
                const int n = n0 + wn*32 + nt*8 + tc;
                const int hh = n >> 6, d = n & 63;
                const float bz0 = __ldg(bias + n), bz1 = __ldg(bias + n + 1);
                const float q0 = (acc[mt][nt][0] + bz0) * 0.125f;
                const float q1 = (acc[mt][nt][1] + bz1) * 0.125f;
                const float q2 = (acc[mt][nt][2] + bz0) * 0.125f;
                const float q3 = (acc[mt][nt][3] + bz1) * 0.125f;
                const size_t i0 = (((size_t)(bb0*H_ + hh))*L_ + l0v)*DK_ + d;
                const size_t i1 = (((size_t)(bb1*H_ + hh))*L_ + l1v)*DK_ + d;
                *(uint32_t*)(g_Qh + i0) = pack_hi2(q0, q1);
                *(uint32_t*)(g_Ql + i0) = pack_rn2(q0 - hi_part(q0), q1 - hi_part(q1));
                *(uint32_t*)(g_Qh + i1) = pack_hi2(q2, q3);
                *(uint32_t*)(g_Ql + i1) = pack_rn2(q2 - hi_part(q2), q3 - hi_part(q3));
            }
        }
    } else {
        unsigned char* Hs = (which == 1) ? g_Khs : g_Vhs;
        unsigned char* Ls = (which == 1) ? g_Kls : g_Vls;
#pragma unroll
        for (int mt = 0; mt < 2; mt++) {
            const int r0 = m0 + wm*32 + mt*16 + g, r1 = r0 + 8;
            const int bb0 = r0 >> 12, l0v = r0 & (L_-1);
            const int bb1 = r1 >> 12, l1v = r1 & (L_-1);
            const int p0 = g_ipos[bb0][l0v];
            const int p1 = g_ipos[bb1][l1v];
#pragma unroll
            for (int nt = 0; nt < 4; nt++) {
                const int n = n0 + wn*32 + nt*8 + tc;
                const int hh = n >> 6, d = n & 63;
                const float bz0 = __ldg(bias + n), bz1 = __ldg(bias + n + 1);
                if (p0 >= 0) {
                    const float v0 = acc[mt][nt][0] + bz0, v1 = acc[mt][nt][1] + bz1;
                    const size_t tb = ((size_t)(bb0*H_ + hh)*NT_ + (p0 >> 6)) * 8192;
                    const uint32_t sw = swz(p0 & 63, d * 2);
                    *(uint32_t*)(Hs + tb + sw) = pack_hi2(v0, v1);
                    *(uint32_t*)(Ls + tb + sw) =
                        pack_rn2(v0 - hi_part(v0), v1 - hi_part(v1));
                }
                if (p1 >= 0) {
                    const float v2 = acc[mt][nt][2] + bz0, v3 = acc[mt][nt][3] + bz1;
                    const size_t tb = ((size_t)(bb1*H_ + hh)*NT_ + (p1 >> 6)) * 8192;
                    const uint32_t sw = swz(p1 & 63, d * 2);
                    *(uint32_t*)(Hs + tb + sw) = pack_hi2(v2, v3);
                    *(uint32_t*)(Ls + tb + sw) =
                        pack_rn2(v2 - hi_part(v2), v3 - hi_part(v3));
                }
            }
        }
    }
}

// Output projection: d_out = O @ Wo^T + bo, plain [M,512].
__global__ __launch_bounds__(256, 2) void out_gemm_tc(
    const float* __restrict__ bo, float* __restrict__ outp)
{
    const unsigned short* Wh = g_Wh + (size_t)3 * D_ * D_;
    const unsigned short* Wl = g_Wl + (size_t)3 * D_ * D_;

    GEMM_TC_SMEM(g_Oh, g_Ol, Wh, Wl)

#pragma unroll
    for (int mt = 0; mt < 2; mt++) {
        const int r0 = m0 + wm*32 + mt*16 + g, r1 = r0 + 8;
#pragma unroll
        for (int nt = 0; nt < 4; nt++) {
            const int n = n0 + wn*32 + nt*8 + tc;
            const float bz0 = __ldg(bo + n), bz1 = __ldg(bo + n + 1);
            *(float2*)(outp + (size_t)r0*D_ + n) =
                make_float2(acc[mt][nt][0] + bz0, acc[mt][nt][1] + bz1);
            *(float2*)(outp + (size_t)r1*D_ + n) =
                make_float2(acc[mt][nt][2] + bz0, acc[mt][nt][3] + bz1);
        }
    }
}

// ---------------------------------------------------------------------------
// Mask compaction: writes inverse map l -> compacted position (or -1).
// ---------------------------------------------------------------------------
__global__ __launch_bounds__(1024) void compact_mask(const int* __restrict__ mask)
{
    __shared__ int warp_sums[32];
    const int b = blockIdx.x;
    const int t = threadIdx.x;
    const int lane = t & 31;
    const int wid  = t >> 5;
    const int* m = mask + b * L_;

    int v[4], loc[4], cnt = 0;
#pragma unroll
    for (int i = 0; i < 4; i++) {
        v[i] = (m[t * 4 + i] != 0);
        loc[i] = cnt;
        cnt += v[i];
    }
    int wp = cnt;
#pragma unroll
    for (int off = 1; off < 32; off <<= 1) {
        int n = __shfl_up_sync(0xFFFFFFFF, wp, off);
        if (lane >= off) wp += n;
    }
    wp -= cnt;
    if (lane == 31) warp_sums[wid] = wp + cnt;
    __syncthreads();
    if (wid == 0) {
        int s = warp_sums[lane];
        int ws = s;
#pragma unroll
        for (int off = 1; off < 32; off <<= 1) {
            int n = __shfl_up_sync(0xFFFFFFFF, ws, off);
            if (lane >= off) ws += n;
        }
        warp_sums[lane] = ws - s;
        if (lane == 31) g_nvalid[b] = ws;
    }
    __syncthreads();
    const int base = warp_sums[wid] + wp;
#pragma unroll
    for (int i = 0; i < 4; i++)
        g_ipos[b][t * 4 + i] = v[i] ? (base + loc[i]) : -1;
}

// ---------------------------------------------------------------------------
// Tensor-core flash attention: 3-stage cp.async ring (one sync per tile),
// split bf16, fixed-shift softmax (shift=16; scores bounded by |s|<=8).
// P kept as 2-term split (Ph + Pl) — single-bf16 P is pinned at ~1e-3 error
// (falsified in R15); the 2-term form is required for correctness margin.
// smem 96KB = 3 stages x [Kh|Kl|Vh|Vl] 8KB each.
// ---------------------------------------------------------------------------
__global__ __launch_bounds__(256, 2) void flash_attn()
{
    extern __shared__ unsigned char smem[];
    const int t    = threadIdx.x;
    const int lane = t & 31;
    const int warp = t >> 5;
    const int h    = blockIdx.y;
    const int b    = blockIdx.z;
    const int rowbase = blockIdx.x * 128 + warp * 16;
    const size_t bh = (size_t)(b * H_ + h) * L_;
    const int nv = g_nvalid[b];
    const int ntiles = (nv + 63) >> 6;

    const int g  = lane >> 2;
    const int tc = (lane & 3) * 2;

    const uint32_t sb = smem_u32(smem);

    // Q fragments: direct split-bf16 loads (pre-scaled in qkv epilogue)
    uint32_t Ah[4][4], Al[4][4];
#pragma unroll
    for (int ks = 0; ks < 4; ks++) {
#pragma unroll
        for (int bhf = 0; bhf < 2; bhf++) {
#pragma unroll
            for (int rhf = 0; rhf < 2; rhf++) {
                const int row = rowbase + g + rhf * 8;
                const size_t idx = (bh + row) * DK_ + ks * 16 + bhf * 8 + tc;
                const int r = rhf + 2 * bhf;
                Ah[ks][r] = *(const uint32_t*)(g_Qh + idx);
                Al[ks][r] = *(const uint32_t*)(g_Ql + idx);
            }
        }
    }

    float O[8][4];
#pragma unroll
    for (int nt = 0; nt < 8; nt++)
#pragma unroll
        for (int c = 0; c < 4; c++) O[nt][c] = 0.0f;

    float lrun0 = 0.0f, lrun1 = 0.0f;

    const size_t tbase = (size_t)(b * H_ + h) * NT_ * 8192;

    #define ISSUE_TILE(i, sidx) do {                                          \
        const size_t go = tbase + (size_t)(i) * 8192;                         \
        const uint32_t stb = sb + (uint32_t)(sidx) * 32768;                   \
        _Pragma("unroll")                                                     \
        for (int r = 0; r < 2; r++) {                                         \
            const uint32_t off = (uint32_t)(t * 16 + r * 4096);               \
            cpasync16(stb +     0 + off, g_Khs + go + off);                   \
            cpasync16(stb +  8192 + off, g_Kls + go + off);                   \
            cpasync16(stb + 16384 + off, g_Vhs + go + off);                   \
            cpasync16(stb + 24576 + off, g_Vls + go + off);                   \
        }                                                                     \
        asm volatile("cp.async.commit_group;");                               \
    } while (0)

    ISSUE_TILE(0, 0);
    if (ntiles > 1) ISSUE_TILE(1, 1);

    int s = 0;
    for (int i = 0; i < ntiles; i++) {
        __syncthreads();   // all warps done with stage (i-1)%3 == (i+2)%3
        if (i + 2 < ntiles) {
            const int s2 = (s + 2 >= 3) ? (s - 1) : (s + 2);
            ISSUE_TILE(i + 2, s2);
            asm volatile("cp.async.wait_group 2;");
        } else if (i + 1 < ntiles) {
            asm volatile("cp.async.wait_group 1;");
        } else {
            asm volatile("cp.async.wait_group 0;");
        }

        const uint32_t bKh = sb + (uint32_t)s * 32768;
        const uint32_t bKl = bKh + 8192;
        const uint32_t bVh = bKh + 16384;
        const uint32_t bVl = bKh + 24576;
        const int rem = nv - i * 64;

        float S[8][4];
#pragma unroll
        for (int nt = 0; nt < 8; nt++)
#pragma unroll
            for (int c = 0; c < 4; c++) S[nt][c] = 0.0f;

#pragma unroll
        for (int ks = 0; ks < 4; ks++) {
#pragma unroll
            for (int u = 0; u < 4; u++) {
                const int mm = lane >> 3, ii = lane & 7;
                const int key = u * 16 + (mm >> 1) * 8 + ii;
                const int dby = (ks * 16 + (mm & 1) * 8) * 2;
                const uint32_t po = swz(key, dby);
                uint32_t h0, h1, h2, h3, l0, l1, l2, l3;
                ldsm4(h0, h1, h2, h3, bKh + po);
                ldsm4(l0, l1, l2, l3, bKl + po);
                mma16816(S[2*u],   Ah[ks], h0, h1);
                mma16816(S[2*u+1], Ah[ks], h2, h3);
                mma16816(S[2*u],   Ah[ks], l0, l1);
                mma16816(S[2*u+1], Ah[ks], l2, l3);
                mma16816(S[2*u],   Al[ks], h0, h1);
                mma16816(S[2*u+1], Al[ks], h2, h3);
            }
        }

        if (rem < 64) {
#pragma unroll
            for (int nt = 0; nt < 8; nt++) {
                const int c0 = nt * 8 + tc;
                if (c0     >= rem) { S[nt][0] = -1.0e30f; S[nt][2] = -1.0e30f; }
                if (c0 + 1 >= rem) { S[nt][1] = -1.0e30f; S[nt][3] = -1.0e30f; }
            }
        }

        // fixed-shift softmax: p = exp(s - 16); accumulate l
#pragma unroll
        for (int nt = 0; nt < 8; nt++) {
            S[nt][0] = __expf(S[nt][0] - 16.0f);
            S[nt][1] = __expf(S[nt][1] - 16.0f);
            S[nt][2] = __expf(S[nt][2] - 16.0f);
            S[nt][3] = __expf(S[nt][3] - 16.0f);
            lrun0 += S[nt][0] + S[nt][1];
            lrun1 += S[nt][2] + S[nt][3];
        }

#pragma unroll
        for (int kv = 0; kv < 4; kv++) {
            uint32_t Ph[4], Pl[4];
            const float* s0 = S[2*kv];
            const float* s1 = S[2*kv+1];
            Ph[0] = pack_hi2(s0[0], s0[1]);
            Ph[1] = pack_hi2(s0[2], s0[3]);
            Ph[2] = pack_hi2(s1[0], s1[1]);
            Ph[3] = pack_hi2(s1[2], s1[3]);
            Pl[0] = pack_rn2(s0[0]-hi_part(s0[0]), s0[1]-hi_part(s0[1]));
            Pl[1] = pack_rn2(s0[2]-hi_part(s0[2]), s0[3]-hi_part(s0[3]));
            Pl[2] = pack_rn2(s1[0]-hi_part(s1[0]), s1[1]-hi_part(s1[1]));
            Pl[3] = pack_rn2(s1[2]-hi_part(s1[2]), s1[3]-hi_part(s1[3]));
#pragma unroll
            for (int dt = 0; dt < 4; dt++) {
                const int mm = lane >> 3, ii = lane & 7;
                const int key = kv * 16 + (mm & 1) * 8 + ii;
                const int dby = (dt * 16 + (mm >> 1) * 8) * 2;
                const uint32_t po = swz(key, dby);
                uint32_t h0, h1, h2, h3, l0, l1, l2, l3;
                ldsm4t(h0, h1, h2, h3, bVh + po);
                ldsm4t(l0, l1, l2, l3, bVl + po);
                mma16816(O[2*dt],   Ph, h0, h1);
                mma16816(O[2*dt+1], Ph, h2, h3);
                mma16816(O[2*dt],   Ph, l0, l1);
                mma16816(O[2*dt+1], Ph, l2, l3);
                mma16816(O[2*dt],   Pl, h0, h1);
                mma16816(O[2*dt+1], Pl, h2, h3);
            }
        }
        s = (s == 2) ? 0 : (s + 1);
    }

    lrun0 += __shfl_xor_sync(0xFFFFFFFF, lrun0, 1);
    lrun0 += __shfl_xor_sync(0xFFFFFFFF, lrun0, 2);
    lrun1 += __shfl_xor_sync(0xFFFFFFFF, lrun1, 1);
    lrun1 += __shfl_xor_sync(0xFFFFFFFF, lrun1, 2);
    const float inv0 = 1.0f / lrun0, inv1 = 1.0f / lrun1;
    const int row0 = rowbase + g, row1 = row0 + 8;
#pragma unroll
    for (int nt = 0; nt < 8; nt++) {
        const int col = h * DK_ + nt * 8 + tc;
        const float v0 = O[nt][0] * inv0, v1 = O[nt][1] * inv0;
        const float v2 = O[nt][2] * inv1, v3 = O[nt][3] * inv1;
        const size_t p0 = ((size_t)b * L_ + row0) * D_ + col;
        const size_t p1 = ((size_t)b * L_ + row1) * D_ + col;
        *(uint32_t*)(g_Oh + p0) = pack_hi2(v0, v1);
        *(uint32_t*)(g_Ol + p0) = pack_rn2(v0 - hi_part(v0), v1 - hi_part(v1));
        *(uint32_t*)(g_Oh + p1) = pack_hi2(v2, v3);
        *(uint32_t*)(g_Ol + p1) = pack_rn2(v2 - hi_part(v2), v3 - hi_part(v3));
    }
    #undef ISSUE_TILE
}

// ---------------------------------------------------------------------------
// kernel_launch
// ---------------------------------------------------------------------------
extern "C" void kernel_launch(void* const* d_in, const int* in_sizes, int n_in,
                              void* d_out, int out_size)
{
    (void)in_sizes; (void)n_in; (void)out_size;
    const float* x    = (const float*)d_in[0];
    const int*   mask = (const int*)  d_in[1];
    const float* Wq   = (const float*)d_in[2];
    const float* bq   = (const float*)d_in[3];
    const float* Wk   = (const float*)d_in[4];
    const float* bk   = (const float*)d_in[5];
    const float* Wv   = (const float*)d_in[6];
    const float* bv   = (const float*)d_in[7];
    const float* Wo   = (const float*)d_in[8];
    const float* bo   = (const float*)d_in[9];
    float* out = (float*)d_out;

    cudaFuncSetAttribute(flash_attn, cudaFuncAttributeMaxDynamicSharedMemorySize, 98304);
    cudaFuncSetAttribute(qkv_gemm_tc, cudaFuncAttributeMaxDynamicSharedMemorySize, 98304);
    cudaFuncSetAttribute(out_gemm_tc, cudaFuncAttributeMaxDynamicSharedMemorySize, 98304);

    unsigned short *xh, *xl, *wh, *wl;
    cudaGetSymbolAddress((void**)&xh, g_xh);
    cudaGetSymbolAddress((void**)&xl, g_xl);
    cudaGetSymbolAddress((void**)&wh, g_Wh);
    cudaGetSymbolAddress((void**)&wl, g_Wl);

    split_f32<<<(M_*D_)/(256*8), 256>>>(x, xh, xl);
    dim3 gw((D_*D_)/(256*8), 4);
    split_w4<<<gw, 256>>>(Wq, Wk, Wv, Wo, wh, wl);

    compact_mask<<<B_, 1024>>>(mask);

    dim3 gp(D_ / 64, M_ / 128, 3);
    qkv_gemm_tc<<<gp, 256, 98304>>>(bq, bk, bv);

    dim3 ga(L_ / 128, H_, B_);
    flash_attn<<<ga, 256, 98304>>>();

    dim3 go(D_ / 64, M_ / 128, 1);
    out_gemm_tc<<<go, 256, 98304>>>(bo, out);
}

// round 17
// speedup vs baseline: 1.2118x; 1.2118x over previous
#include <cuda_runtime.h>
#include <cuda_bf16.h>
#include <cuda_fp16.h>
#include <cstdint>
#include <cstddef>

// Problem constants
#define B_  2
#define L_  4096
#define D_  512
#define H_  8
#define DK_ 64
#define M_  (B_*L_)
#define NT_ (L_/64)

// Scratch (static device globals — allocation-free per harness rules)
__device__ __align__(16) unsigned short g_Qh[(size_t)B_*H_*L_*DK_];  // fp16, pre-scaled 1/8
__device__ __align__(16) unsigned short g_xh[(size_t)M_*D_];
__device__ __align__(16) unsigned short g_xl[(size_t)M_*D_];
__device__ __align__(16) unsigned short g_Wh[(size_t)4*D_*D_];   // Wq,Wk,Wv,Wo (bf16 split)
__device__ __align__(16) unsigned short g_Wl[(size_t)4*D_*D_];
__device__ __align__(16) unsigned short g_Oh[(size_t)M_*D_];     // bf16 split (for out GEMM)
__device__ __align__(16) unsigned short g_Ol[(size_t)M_*D_];
// Pre-swizzled split-FP16 K/V tiles (zero-init → safe tails; masked rows never written)
__device__ __align__(16) unsigned char g_Khs[(size_t)B_*H_*NT_*8192];
__device__ __align__(16) unsigned char g_Kls[(size_t)B_*H_*NT_*8192];
__device__ __align__(16) unsigned char g_Vhs[(size_t)B_*H_*NT_*8192];
__device__ __align__(16) unsigned char g_Vls[(size_t)B_*H_*NT_*8192];
__device__ int g_ipos[B_][L_];   // l -> compacted position, or -1 if masked
__device__ int g_nvalid[B_];

// ---------------------------------------------------------------------------
// bf16-split + fp16 + MMA helpers
// ---------------------------------------------------------------------------
__device__ __forceinline__ uint32_t pack_hi2(float x0, float x1) {
    uint32_t r;
    asm("prmt.b32 %0, %1, %2, 0x7632;" : "=r"(r)
        : "r"(__float_as_uint(x0)), "r"(__float_as_uint(x1)));
    return r;
}
__device__ __forceinline__ float hi_part(float x) {
    return __uint_as_float(__float_as_uint(x) & 0xFFFF0000u);
}
__device__ __forceinline__ uint32_t pack_rn2(float x0, float x1) {
    uint32_t r;
    asm("cvt.rn.bf16x2.f32 %0, %1, %2;" : "=r"(r) : "f"(x1), "f"(x0));
    return r;
}
// fp16x2 pack: lo half = x0, hi half = x1
__device__ __forceinline__ uint32_t pack_f16x2(float x0, float x1) {
    uint32_t r;
    asm("cvt.rn.f16x2.f32 %0, %1, %2;" : "=r"(r) : "f"(x1), "f"(x0));
    return r;
}
__device__ __forceinline__ float2 unpack_f16x2(uint32_t v) {
    __half2 h = *reinterpret_cast<__half2*>(&v);
    return __half22float2(h);
}
// 2-term fp16 split of a pair
__device__ __forceinline__ void f16_split2(float a, float b, uint32_t& Hv, uint32_t& Lv) {
    Hv = pack_f16x2(a, b);
    const float2 hb = unpack_f16x2(Hv);
    Lv = pack_f16x2(a - hb.x, b - hb.y);
}
__device__ __forceinline__ void mma16816(float* d, const uint32_t* a,
                                         uint32_t b0, uint32_t b1) {
    asm volatile(
        "mma.sync.aligned.m16n8k16.row.col.f32.bf16.bf16.f32 "
        "{%0,%1,%2,%3},{%4,%5,%6,%7},{%8,%9},{%0,%1,%2,%3};"
        : "+f"(d[0]), "+f"(d[1]), "+f"(d[2]), "+f"(d[3])
        : "r"(a[0]), "r"(a[1]), "r"(a[2]), "r"(a[3]), "r"(b0), "r"(b1));
}
__device__ __forceinline__ void mma16816h(float* d, const uint32_t* a,
                                          uint32_t b0, uint32_t b1) {
    asm volatile(
        "mma.sync.aligned.m16n8k16.row.col.f32.f16.f16.f32 "
        "{%0,%1,%2,%3},{%4,%5,%6,%7},{%8,%9},{%0,%1,%2,%3};"
        : "+f"(d[0]), "+f"(d[1]), "+f"(d[2]), "+f"(d[3])
        : "r"(a[0]), "r"(a[1]), "r"(a[2]), "r"(a[3]), "r"(b0), "r"(b1));
}
__device__ __forceinline__ void ldsm4(uint32_t& r0, uint32_t& r1, uint32_t& r2,
                                      uint32_t& r3, uint32_t addr) {
    asm volatile("ldmatrix.sync.aligned.m8n8.x4.shared.b16 {%0,%1,%2,%3}, [%4];"
                 : "=r"(r0), "=r"(r1), "=r"(r2), "=r"(r3) : "r"(addr));
}
__device__ __forceinline__ void ldsm4t(uint32_t& r0, uint32_t& r1, uint32_t& r2,
                                       uint32_t& r3, uint32_t addr) {
    asm volatile("ldmatrix.sync.aligned.m8n8.x4.trans.shared.b16 {%0,%1,%2,%3}, [%4];"
                 : "=r"(r0), "=r"(r1), "=r"(r2), "=r"(r3) : "r"(addr));
}
__device__ __forceinline__ uint32_t smem_u32(const void* p) {
    return (uint32_t)__cvta_generic_to_shared(p);
}
__device__ __forceinline__ void cpasync16(uint32_t saddr, const void* gptr) {
    asm volatile("cp.async.cg.shared.global [%0], [%1], 16;" :: "r"(saddr), "l"(gptr));
}
__device__ __forceinline__ uint32_t swz(int key, int dimbyte) {
    uint32_t off = (uint32_t)(key * 128 + dimbyte);
    return off ^ ((uint32_t)(key & 7) << 4);
}

// ---------------------------------------------------------------------------
// fp32 -> split bf16 converters (projection operands)
// ---------------------------------------------------------------------------
__global__ __launch_bounds__(256) void split_f32(
    const float* __restrict__ src,
    unsigned short* __restrict__ dh, unsigned short* __restrict__ dl)
{
    const size_t i = ((size_t)blockIdx.x * 256 + threadIdx.x) * 8;
    const float4 a = *(const float4*)(src + i);
    const float4 b = *(const float4*)(src + i + 4);
    const float f[8] = {a.x, a.y, a.z, a.w, b.x, b.y, b.z, b.w};
    uint4 Hv, Lv;
    Hv.x = pack_hi2(f[0], f[1]); Hv.y = pack_hi2(f[2], f[3]);
    Hv.z = pack_hi2(f[4], f[5]); Hv.w = pack_hi2(f[6], f[7]);
    Lv.x = pack_rn2(f[0]-hi_part(f[0]), f[1]-hi_part(f[1]));
    Lv.y = pack_rn2(f[2]-hi_part(f[2]), f[3]-hi_part(f[3]));
    Lv.z = pack_rn2(f[4]-hi_part(f[4]), f[5]-hi_part(f[5]));
    Lv.w = pack_rn2(f[6]-hi_part(f[6]), f[7]-hi_part(f[7]));
    *(uint4*)(dh + i) = Hv;
    *(uint4*)(dl + i) = Lv;
}

__global__ __launch_bounds__(256) void split_w4(
    const float* __restrict__ Wq, const float* __restrict__ Wk,
    const float* __restrict__ Wv, const float* __restrict__ Wo,
    unsigned short* __restrict__ dh, unsigned short* __restrict__ dl)
{
    const int which = blockIdx.y;
    const float* src = (which == 0) ? Wq : (which == 1) ? Wk : (which == 2) ? Wv : Wo;
    const size_t base = (size_t)which * D_ * D_;
    const size_t i = ((size_t)blockIdx.x * 256 + threadIdx.x) * 8;
    const float4 a = *(const float4*)(src + i);
    const float4 b = *(const float4*)(src + i + 4);
    const float f[8] = {a.x, a.y, a.z, a.w, b.x, b.y, b.z, b.w};
    uint4 Hv, Lv;
    Hv.x = pack_hi2(f[0], f[1]); Hv.y = pack_hi2(f[2], f[3]);
    Hv.z = pack_hi2(f[4], f[5]); Hv.w = pack_hi2(f[6], f[7]);
    Lv.x = pack_rn2(f[0]-hi_part(f[0]), f[1]-hi_part(f[1]));
    Lv.y = pack_rn2(f[2]-hi_part(f[2]), f[3]-hi_part(f[3]));
    Lv.z = pack_rn2(f[4]-hi_part(f[4]), f[5]-hi_part(f[5]));
    Lv.w = pack_rn2(f[6]-hi_part(f[6]), f[7]-hi_part(f[7]));
    *(uint4*)(dh + base + i) = Hv;
    *(uint4*)(dl + base + i) = Lv;
}

// ---------------------------------------------------------------------------
// Tensor-core split-bf16 GEMM core (cp.async double-buffered, BK=64).
// Block 128x64, 8 warps (4m x 2n), warp tile 32x32 = 2x4 m16n8 tiles. (unchanged)
// ---------------------------------------------------------------------------
#define GEMM_TC_SMEM(AHP, ALP, WHP, WLP)                                      \
    extern __shared__ unsigned char smem[];                                   \
    const int t = threadIdx.x;                                                \
    const int lane = t & 31, warp = t >> 5;                                   \
    const int wm = warp & 3, wn = warp >> 2;                                  \
    const int m0 = blockIdx.y * 128;                                          \
    const int n0 = blockIdx.x * 64;                                           \
    const int g = lane >> 2, tc = (lane & 3) * 2;                             \
    const uint32_t sb = smem_u32(smem);                                       \
    const int mm = lane >> 3, ii = lane & 7;                                  \
    float acc[2][4][4];                                                       \
    _Pragma("unroll")                                                         \
    for (int i = 0; i < 2; i++)                                               \
        _Pragma("unroll")                                                     \
        for (int j = 0; j < 4; j++)                                           \
            _Pragma("unroll")                                                 \
            for (int c = 0; c < 4; c++) acc[i][j][c] = 0.0f;                  \
    uint32_t sofA[4]; const unsigned char* gA[4];                             \
    _Pragma("unroll")                                                         \
    for (int r = 0; r < 4; r++) {                                             \
        const int item = t + r * 256;                                         \
        const int rowx = item >> 3, oc = item & 7;                            \
        sofA[r] = swz(rowx, oc * 16);                                         \
        gA[r] = (const unsigned char*)(AHP)                                   \
                + ((size_t)(m0 + rowx) * D_ + oc * 8) * 2;                    \
    }                                                                         \
    uint32_t sofW[2]; const unsigned char* gW[2];                             \
    _Pragma("unroll")                                                         \
    for (int r = 0; r < 2; r++) {                                             \
        const int item = t + r * 256;                                         \
        const int rowx = item >> 3, oc = item & 7;                            \
        sofW[r] = swz(rowx, oc * 16);                                         \
        gW[r] = (const unsigned char*)(WHP)                                   \
                + ((size_t)(n0 + rowx) * D_ + oc * 8) * 2;                    \
    }                                                                         \
    const ptrdiff_t dAL = (const unsigned char*)(ALP) - (const unsigned char*)(AHP); \
    const ptrdiff_t dWL = (const unsigned char*)(WLP) - (const unsigned char*)(WHP); \
    _Pragma("unroll")                                                         \
    for (int r = 0; r < 4; r++) {                                             \
        cpasync16(sb +     0 + sofA[r], gA[r]);                               \
        cpasync16(sb + 32768 + sofA[r], gA[r] + dAL);                         \
    }                                                                         \
    _Pragma("unroll")                                                         \
    for (int r = 0; r < 2; r++) {                                             \
        cpasync16(sb + 65536 + sofW[r], gW[r]);                               \
        cpasync16(sb + 81920 + sofW[r], gW[r] + dWL);                         \
    }                                                                         \
    asm volatile("cp.async.commit_group;");                                   \
    _Pragma("unroll")                                                         \
    for (int kt = 0; kt < 8; kt++) {                                          \
        const int st = kt & 1;                                                \
        if (kt + 1 < 8) {                                                     \
            const uint32_t sA = (uint32_t)((st ^ 1) * 16384);                 \
            const uint32_t sW = (uint32_t)((st ^ 1) * 8192);                  \
            const size_t kb = (size_t)(kt + 1) * 128;                         \
            _Pragma("unroll")                                                 \
            for (int r = 0; r < 4; r++) {                                     \
                cpasync16(sb +     0 + sA + sofA[r], gA[r] + kb);             \
                cpasync16(sb + 32768 + sA + sofA[r], gA[r] + dAL + kb);       \
            }                                                                 \
            _Pragma("unroll")                                                 \
            for (int r = 0; r < 2; r++) {                                     \
                cpasync16(sb + 65536 + sW + sofW[r], gW[r] + kb);             \
                cpasync16(sb + 81920 + sW + sofW[r], gW[r] + dWL + kb);       \
            }                                                                 \
            asm volatile("cp.async.commit_group;");                           \
            asm volatile("cp.async.wait_group 1;");                           \
        } else {                                                              \
            asm volatile("cp.async.wait_group 0;");                           \
        }                                                                     \
        __syncthreads();                                                      \
        const uint32_t bAh = sb +     0 + st * 16384;                         \
        const uint32_t bAl = sb + 32768 + st * 16384;                         \
        const uint32_t bWh = sb + 65536 + st * 8192;                          \
        const uint32_t bWl = sb + 81920 + st * 8192;                          \
        _Pragma("unroll")                                                     \
        for (int ks = 0; ks < 4; ks++) {                                      \
            const int dby = ks * 32 + (mm & 1) * 16;                          \
            uint32_t ah[2][4], al[2][4];                                      \
            _Pragma("unroll")                                                 \
            for (int mt = 0; mt < 2; mt++) {                                  \
                const int key = wm * 32 + mt * 16 + (mm >> 1) * 8 + ii;       \
                const uint32_t po = swz(key, dby);                            \
                uint32_t r0, r1, r2, r3;                                      \
                ldsm4(r0, r1, r2, r3, bAh + po);                              \
                ah[mt][0] = r0; ah[mt][1] = r2; ah[mt][2] = r1; ah[mt][3] = r3; \
                ldsm4(r0, r1, r2, r3, bAl + po);                              \
                al[mt][0] = r0; al[mt][1] = r2; al[mt][2] = r1; al[mt][3] = r3; \
            }                                                                 \
            uint32_t whf[2][4], wlf[2][4];                                    \
            _Pragma("unroll")                                                 \
            for (int ng = 0; ng < 2; ng++) {                                  \
                const int key = wn * 32 + ng * 16 + (mm >> 1) * 8 + ii;       \
                const uint32_t po = swz(key, dby);                            \
                ldsm4(whf[ng][0], whf[ng][1], whf[ng][2], whf[ng][3], bWh + po); \
                ldsm4(wlf[ng][0], wlf[ng][1], wlf[ng][2], wlf[ng][3], bWl + po); \
            }                                                                 \
            _Pragma("unroll")                                                 \
            for (int mt = 0; mt < 2; mt++)                                    \
                _Pragma("unroll")                                             \
                for (int nt = 0; nt < 4; nt++)                                \
                    mma16816(acc[mt][nt], ah[mt],                             \
                             whf[nt>>1][(nt&1)*2], whf[nt>>1][(nt&1)*2+1]);   \
            _Pragma("unroll")                                                 \
            for (int mt = 0; mt < 2; mt++)                                    \
                _Pragma("unroll")                                             \
                for (int nt = 0; nt < 4; nt++)                                \
                    mma16816(acc[mt][nt], ah[mt],                             \
                             wlf[nt>>1][(nt&1)*2], wlf[nt>>1][(nt&1)*2+1]);   \
            _Pragma("unroll")                                                 \
            for (int mt = 0; mt < 2; mt++)                                    \
                _Pragma("unroll")                                             \
                for (int nt = 0; nt < 4; nt++)                                \
                    mma16816(acc[mt][nt], al[mt],                             \
                             whf[nt>>1][(nt&1)*2], whf[nt>>1][(nt&1)*2+1]);   \
        }                                                                     \
        __syncthreads();                                                      \
    }

// QKV projection: Q -> single fp16 pre-scaled [B,H,L,dk]; K/V -> pre-swizzled
// split-FP16 compacted tiles (masked rows skipped; tails stay zero).
__global__ __launch_bounds__(256, 2) void qkv_gemm_tc(
    const float* __restrict__ bq, const float* __restrict__ bk,
    const float* __restrict__ bv)
{
    const int which = blockIdx.z;
    const unsigned short* Wh = g_Wh + (size_t)which * D_ * D_;
    const unsigned short* Wl = g_Wl + (size_t)which * D_ * D_;
    const float* bias = (which == 0) ? bq : ((which == 1) ? bk : bv);

    GEMM_TC_SMEM(g_xh, g_xl, Wh, Wl)

    if (which == 0) {
#pragma unroll
        for (int mt = 0; mt < 2; mt++) {
            const int r0 = m0 + wm*32 + mt*16 + g, r1 = r0 + 8;
            const int bb0 = r0 >> 12, l0v = r0 & (L_-1);
            const int bb1 = r1 >> 12, l1v = r1 & (L_-1);
#pragma unroll
            for (int nt = 0; nt < 4; nt++) {
                const int n = n0 + wn*32 + nt*8 + tc;
                const int hh = n >> 6, d = n & 63;
                const float bz0 = __ldg(bias + n), bz1 = __ldg(bias + n + 1);
                const float q0 = (acc[mt][nt][0] + bz0) * 0.125f;
                const float q1 = (acc[mt][nt][1] + bz1) * 0.125f;
                const float q2 = (acc[mt][nt][2] + bz0) * 0.125f;
                const float q3 = (acc[mt][nt][3] + bz1) * 0.125f;
                const size_t i0 = (((size_t)(bb0*H_ + hh))*L_ + l0v)*DK_ + d;
                const size_t i1 = (((size_t)(bb1*H_ + hh))*L_ + l1v)*DK_ + d;
                *(uint32_t*)(g_Qh + i0) = pack_f16x2(q0, q1);
                *(uint32_t*)(g_Qh + i1) = pack_f16x2(q2, q3);
            }
        }
    } else {
        unsigned char* Hs = (which == 1) ? g_Khs : g_Vhs;
        unsigned char* Ls = (which == 1) ? g_Kls : g_Vls;
#pragma unroll
        for (int mt = 0; mt < 2; mt++) {
            const int r0 = m0 + wm*32 + mt*16 + g, r1 = r0 + 8;
            const int bb0 = r0 >> 12, l0v = r0 & (L_-1);
            const int bb1 = r1 >> 12, l1v = r1 & (L_-1);
            const int p0 = g_ipos[bb0][l0v];
            const int p1 = g_ipos[bb1][l1v];
#pragma unroll
            for (int nt = 0; nt < 4; nt++) {
                const int n = n0 + wn*32 + nt*8 + tc;
                const int hh = n >> 6, d = n & 63;
                const float bz0 = __ldg(bias + n), bz1 = __ldg(bias + n + 1);
                if (p0 >= 0) {
                    const float v0 = acc[mt][nt][0] + bz0, v1 = acc[mt][nt][1] + bz1;
                    const size_t tb = ((size_t)(bb0*H_ + hh)*NT_ + (p0 >> 6)) * 8192;
                    const uint32_t sw = swz(p0 & 63, d * 2);
                    uint32_t Hv, Lv;
                    f16_split2(v0, v1, Hv, Lv);
                    *(uint32_t*)(Hs + tb + sw) = Hv;
                    *(uint32_t*)(Ls + tb + sw) = Lv;
                }
                if (p1 >= 0) {
                    const float v2 = acc[mt][nt][2] + bz0, v3 = acc[mt][nt][3] + bz1;
                    const size_t tb = ((size_t)(bb1*H_ + hh)*NT_ + (p1 >> 6)) * 8192;
                    const uint32_t sw = swz(p1 & 63, d * 2);
                    uint32_t Hv, Lv;
                    f16_split2(v2, v3, Hv, Lv);
                    *(uint32_t*)(Hs + tb + sw) = Hv;
                    *(uint32_t*)(Ls + tb + sw) = Lv;
                }
            }
        }
    }
}

// Output projection: d_out = O @ Wo^T + bo, plain [M,512]. (bf16 split, unchanged)
__global__ __launch_bounds__(256, 2) void out_gemm_tc(
    const float* __restrict__ bo, float* __restrict__ outp)
{
    const unsigned short* Wh = g_Wh + (size_t)3 * D_ * D_;
    const unsigned short* Wl = g_Wl + (size_t)3 * D_ * D_;

    GEMM_TC_SMEM(g_Oh, g_Ol, Wh, Wl)

#pragma unroll
    for (int mt = 0; mt < 2; mt++) {
        const int r0 = m0 + wm*32 + mt*16 + g, r1 = r0 + 8;
#pragma unroll
        for (int nt = 0; nt < 4; nt++) {
            const int n = n0 + wn*32 + nt*8 + tc;
            const float bz0 = __ldg(bo + n), bz1 = __ldg(bo + n + 1);
            *(float2*)(outp + (size_t)r0*D_ + n) =
                make_float2(acc[mt][nt][0] + bz0, acc[mt][nt][1] + bz1);
            *(float2*)(outp + (size_t)r1*D_ + n) =
                make_float2(acc[mt][nt][2] + bz0, acc[mt][nt][3] + bz1);
        }
    }
}

// ---------------------------------------------------------------------------
// Mask compaction: writes inverse map l -> compacted position (or -1).
// ---------------------------------------------------------------------------
__global__ __launch_bounds__(1024) void compact_mask(const int* __restrict__ mask)
{
    __shared__ int warp_sums[32];
    const int b = blockIdx.x;
    const int t = threadIdx.x;
    const int lane = t & 31;
    const int wid  = t >> 5;
    const int* m = mask + b * L_;

    int v[4], loc[4], cnt = 0;
#pragma unroll
    for (int i = 0; i < 4; i++) {
        v[i] = (m[t * 4 + i] != 0);
        loc[i] = cnt;
        cnt += v[i];
    }
    int wp = cnt;
#pragma unroll
    for (int off = 1; off < 32; off <<= 1) {
        int n = __shfl_up_sync(0xFFFFFFFF, wp, off);
        if (lane >= off) wp += n;
    }
    wp -= cnt;
    if (lane == 31) warp_sums[wid] = wp + cnt;
    __syncthreads();
    if (wid == 0) {
        int s = warp_sums[lane];
        int ws = s;
#pragma unroll
        for (int off = 1; off < 32; off <<= 1) {
            int n = __shfl_up_sync(0xFFFFFFFF, ws, off);
            if (lane >= off) ws += n;
        }
        warp_sums[lane] = ws - s;
        if (lane == 31) g_nvalid[b] = ws;
    }
    __syncthreads();
    const int base = warp_sums[wid] + wp;
#pragma unroll
    for (int i = 0; i < 4; i++)
        g_ipos[b][t * 4 + i] = v[i] ? (base + loc[i]) : -1;
}

// ---------------------------------------------------------------------------
// Tensor-core flash attention (fp16): 3-stage cp.async ring, fixed-shift
// softmax (shift=8, fp16-friendly p range). Q single fp16 (rounded),
// K/V 2-term fp16 split, P single fp16 (rounded).
// Same-accumulator MMA distance 4 via u/dt pairing.
// ---------------------------------------------------------------------------
__global__ __launch_bounds__(256, 2) void flash_attn()
{
    extern __shared__ unsigned char smem[];
    const int t    = threadIdx.x;
    const int lane = t & 31;
    const int warp = t >> 5;
    const int h    = blockIdx.y;
    const int b    = blockIdx.z;
    const int rowbase = blockIdx.x * 128 + warp * 16;
    const size_t bh = (size_t)(b * H_ + h) * L_;
    const int nv = g_nvalid[b];
    const int ntiles = (nv + 63) >> 6;

    const int g  = lane >> 2;
    const int tc = (lane & 3) * 2;
    const int mm = lane >> 3, ii = lane & 7;

    const uint32_t sb = smem_u32(smem);

    // Q fragments: single fp16 (pre-scaled in qkv epilogue)
    uint32_t Ah[4][4];
#pragma unroll
    for (int ks = 0; ks < 4; ks++) {
#pragma unroll
        for (int bhf = 0; bhf < 2; bhf++) {
#pragma unroll
            for (int rhf = 0; rhf < 2; rhf++) {
                const int row = rowbase + g + rhf * 8;
                const size_t idx = (bh + row) * DK_ + ks * 16 + bhf * 8 + tc;
                Ah[ks][rhf + 2 * bhf] = *(const uint32_t*)(g_Qh + idx);
            }
        }
    }

    float O[8][4];
#pragma unroll
    for (int nt = 0; nt < 8; nt++)
#pragma unroll
        for (int c = 0; c < 4; c++) O[nt][c] = 0.0f;

    float lrun0 = 0.0f, lrun1 = 0.0f;

    const size_t tbase = (size_t)(b * H_ + h) * NT_ * 8192;

    #define ISSUE_TILE(i, sidx) do {                                          \
        const size_t go = tbase + (size_t)(i) * 8192;                         \
        const uint32_t stb = sb + (uint32_t)(sidx) * 32768;                   \
        _Pragma("unroll")                                                     \
        for (int r = 0; r < 2; r++) {                                         \
            const uint32_t off = (uint32_t)(t * 16 + r * 4096);               \
            cpasync16(stb +     0 + off, g_Khs + go + off);                   \
            cpasync16(stb +  8192 + off, g_Kls + go + off);                   \
            cpasync16(stb + 16384 + off, g_Vhs + go + off);                   \
            cpasync16(stb + 24576 + off, g_Vls + go + off);                   \
        }                                                                     \
        asm volatile("cp.async.commit_group;");                               \
    } while (0)

    ISSUE_TILE(0, 0);
    if (ntiles > 1) ISSUE_TILE(1, 1);

    int s = 0;
    for (int i = 0; i < ntiles; i++) {
        __syncthreads();
        if (i + 2 < ntiles) {
            const int s2 = (s + 2 >= 3) ? (s - 1) : (s + 2);
            ISSUE_TILE(i + 2, s2);
            asm volatile("cp.async.wait_group 2;");
        } else if (i + 1 < ntiles) {
            asm volatile("cp.async.wait_group 1;");
        } else {
            asm volatile("cp.async.wait_group 0;");
        }

        const uint32_t bKh = sb + (uint32_t)s * 32768;
        const uint32_t bKl = bKh + 8192;
        const uint32_t bVh = bKh + 16384;
        const uint32_t bVl = bKh + 24576;
        const int rem = nv - i * 64;

        float S[8][4];
#pragma unroll
        for (int nt = 0; nt < 8; nt++)
#pragma unroll
            for (int c = 0; c < 4; c++) S[nt][c] = 0.0f;

        // ---- S = Q K^T : 2 terms, u-paired for acc distance 4 ----
#pragma unroll
        for (int ks = 0; ks < 4; ks++) {
            const int dby = (ks * 16 + (mm & 1) * 8) * 2;
#pragma unroll
            for (int up = 0; up < 4; up += 2) {
                const int key0 = up * 16 + (mm >> 1) * 8 + ii;
                const int key1 = (up + 1) * 16 + (mm >> 1) * 8 + ii;
                const uint32_t po0 = swz(key0, dby);
                const uint32_t po1 = swz(key1, dby);
                uint32_t h0, h1, h2, h3, h4, h5, h6, h7;
                uint32_t l0, l1, l2, l3, l4, l5, l6, l7;
                ldsm4(h0, h1, h2, h3, bKh + po0);
                ldsm4(h4, h5, h6, h7, bKh + po1);
                ldsm4(l0, l1, l2, l3, bKl + po0);
                ldsm4(l4, l5, l6, l7, bKl + po1);
                mma16816h(S[2*up],   Ah[ks], h0, h1);
                mma16816h(S[2*up+1], Ah[ks], h2, h3);
                mma16816h(S[2*up+2], Ah[ks], h4, h5);
                mma16816h(S[2*up+3], Ah[ks], h6, h7);
                mma16816h(S[2*up],   Ah[ks], l0, l1);
                mma16816h(S[2*up+1], Ah[ks], l2, l3);
                mma16816h(S[2*up+2], Ah[ks], l4, l5);
                mma16816h(S[2*up+3], Ah[ks], l6, l7);
            }
        }

        if (rem < 64) {
#pragma unroll
            for (int nt = 0; nt < 8; nt++) {
                const int c0 = nt * 8 + tc;
                if (c0     >= rem) { S[nt][0] = -1.0e30f; S[nt][2] = -1.0e30f; }
                if (c0 + 1 >= rem) { S[nt][1] = -1.0e30f; S[nt][3] = -1.0e30f; }
            }
        }

        // fixed-shift softmax: p = exp(s - 8)  (p in fp16-normal range)
#pragma unroll
        for (int nt = 0; nt < 8; nt++) {
            S[nt][0] = __expf(S[nt][0] - 8.0f);
            S[nt][1] = __expf(S[nt][1] - 8.0f);
            S[nt][2] = __expf(S[nt][2] - 8.0f);
            S[nt][3] = __expf(S[nt][3] - 8.0f);
            lrun0 += S[nt][0] + S[nt][1];
            lrun1 += S[nt][2] + S[nt][3];
        }

        // ---- O += P V : P single fp16, V 2-term; dt-paired ----
#pragma unroll
        for (int kv = 0; kv < 4; kv++) {
            uint32_t Ph[4];
            const float* s0 = S[2*kv];
            const float* s1 = S[2*kv+1];
            Ph[0] = pack_f16x2(s0[0], s0[1]);
            Ph[1] = pack_f16x2(s0[2], s0[3]);
            Ph[2] = pack_f16x2(s1[0], s1[1]);
            Ph[3] = pack_f16x2(s1[2], s1[3]);
            const int key = kv * 16 + (mm & 1) * 8 + ii;
#pragma unroll
            for (int dtp = 0; dtp < 4; dtp += 2) {
                const int dby0 = (dtp * 16 + (mm >> 1) * 8) * 2;
                const int dby1 = ((dtp + 1) * 16 + (mm >> 1) * 8) * 2;
                const uint32_t po0 = swz(key, dby0);
                const uint32_t po1 = swz(key, dby1);
                uint32_t h0, h1, h2, h3, h4, h5, h6, h7;
                uint32_t l0, l1, l2, l3, l4, l5, l6, l7;
                ldsm4t(h0, h1, h2, h3, bVh + po0);
                ldsm4t(h4, h5, h6, h7, bVh + po1);
                ldsm4t(l0, l1, l2, l3, bVl + po0);
                ldsm4t(l4, l5, l6, l7, bVl + po1);
                mma16816h(O[2*dtp],   Ph, h0, h1);
                mma16816h(O[2*dtp+1], Ph, h2, h3);
                mma16816h(O[2*dtp+2], Ph, h4, h5);
                mma16816h(O[2*dtp+3], Ph, h6, h7);
                mma16816h(O[2*dtp],   Ph, l0, l1);
                mma16816h(O[2*dtp+1], Ph, l2, l3);
                mma16816h(O[2*dtp+2], Ph, l4, l5);
                mma16816h(O[2*dtp+3], Ph, l6, l7);
            }
        }
        s = (s == 2) ? 0 : (s + 1);
    }

    lrun0 += __shfl_xor_sync(0xFFFFFFFF, lrun0, 1);
    lrun0 += __shfl_xor_sync(0xFFFFFFFF, lrun0, 2);
    lrun1 += __shfl_xor_sync(0xFFFFFFFF, lrun1, 1);
    lrun1 += __shfl_xor_sync(0xFFFFFFFF, lrun1, 2);
    const float inv0 = 1.0f / lrun0, inv1 = 1.0f / lrun1;
    const int row0 = rowbase + g, row1 = row0 + 8;
#pragma unroll
    for (int nt = 0; nt < 8; nt++) {
        const int col = h * DK_ + nt * 8 + tc;
        const float v0 = O[nt][0] * inv0, v1 = O[nt][1] * inv0;
        const float v2 = O[nt][2] * inv1, v3 = O[nt][3] * inv1;
        const size_t p0 = ((size_t)b * L_ + row0) * D_ + col;
        const size_t p1 = ((size_t)b * L_ + row1) * D_ + col;
        *(uint32_t*)(g_Oh + p0) = pack_hi2(v0, v1);
        *(uint32_t*)(g_Ol + p0) = pack_rn2(v0 - hi_part(v0), v1 - hi_part(v1));
        *(uint32_t*)(g_Oh + p1) = pack_hi2(v2, v3);
        *(uint32_t*)(g_Ol + p1) = pack_rn2(v2 - hi_part(v2), v3 - hi_part(v3));
    }
    #undef ISSUE_TILE
}

// ---------------------------------------------------------------------------
// kernel_launch
// ---------------------------------------------------------------------------
extern "C" void kernel_launch(void* const* d_in, const int* in_sizes, int n_in,
                              void* d_out, int out_size)
{
    (void)in_sizes; (void)n_in; (void)out_size;
    const float* x    = (const float*)d_in[0];
    const int*   mask = (const int*)  d_in[1];
    const float* Wq   = (const float*)d_in[2];
    const float* bq   = (const float*)d_in[3];
    const float* Wk   = (const float*)d_in[4];
    const float* bk   = (const float*)d_in[5];
    const float* Wv   = (const float*)d_in[6];
    const float* bv   = (const float*)d_in[7];
    const float* Wo   = (const float*)d_in[8];
    const float* bo   = (const float*)d_in[9];
    float* out = (float*)d_out;

    cudaFuncSetAttribute(flash_attn, cudaFuncAttributeMaxDynamicSharedMemorySize, 98304);
    cudaFuncSetAttribute(qkv_gemm_tc, cudaFuncAttributeMaxDynamicSharedMemorySize, 98304);
    cudaFuncSetAttribute(out_gemm_tc, cudaFuncAttributeMaxDynamicSharedMemorySize, 98304);

    unsigned short *xh, *xl, *wh, *wl;
    cudaGetSymbolAddress((void**)&xh, g_xh);
    cudaGetSymbolAddress((void**)&xl, g_xl);
    cudaGetSymbolAddress((void**)&wh, g_Wh);
    cudaGetSymbolAddress((void**)&wl, g_Wl);

    split_f32<<<(M_*D_)/(256*8), 256>>>(x, xh, xl);
    dim3 gw((D_*D_)/(256*8), 4);
    split_w4<<<gw, 256>>>(Wq, Wk, Wv, Wo, wh, wl);

    compact_mask<<<B_, 1024>>>(mask);

    dim3 gp(D_ / 64, M_ / 128, 3);
    qkv_gemm_tc<<<gp, 256, 98304>>>(bq, bk, bv);

    dim3 ga(L_ / 128, H_, B_);
    flash_attn<<<ga, 256, 98304>>>();

    dim3 go(D_ / 64, M_ / 128, 1);
    out_gemm_tc<<<go, 256, 98304>>>(bo, out);
}